// round 3
// baseline (speedup 1.0000x reference)
#include <cuda_runtime.h>

// ---------------------------------------------------------------------------
// QuantumRegressionModel: 16-qubit statevector sim, batch 64.
//
// Math exploited:
//  * Per layer, the 16 single-qubit rotations commute -> split into
//    Pass B (wires 0..3 = bits 15..12) and Pass A (wires 4..15 = bits 11..0).
//  * The CNOT chain CNOT(0,1)..CNOT(14,15) is the Gray-code permutation:
//      psi_after[b] = psi_before[b ^ (b>>1)]
//    fused as a gather into the next Pass B (layers 2,3) and into the final
//    Pauli-Z sign pattern (layer 3): bit q of final index = parity(s>>(15-q)).
// ---------------------------------------------------------------------------

#define NQ    16
#define DIM   65536
#define BATCH 64

__device__ float2 g_buf0[BATCH * DIM];   // 32 MB
__device__ float2 g_buf1[BATCH * DIM];   // 32 MB
__device__ __align__(16) float g_gates[3 * 16 * 8];
__device__ float g_partial[BATCH * 16];

// ---------------------------------------------------------------------------
// Gate precompute: U = Rz(tz) Ry(ty) Rx(tx), stored as
// (u00r,u00i,u01r,u01i, u10r,u10i,u11r,u11i)
// ---------------------------------------------------------------------------
__global__ void prep_gates(const float* __restrict__ vp) {
    int g = threadIdx.x;
    if (g >= 48) return;
    float tx = vp[g * 6 + 0], ty = vp[g * 6 + 1], tz = vp[g * 6 + 2];
    float cx, sx, cy, sy, cz, sz;
    sincosf(tx * 0.5f, &sx, &cx);
    sincosf(ty * 0.5f, &sy, &cy);
    sincosf(tz * 0.5f, &sz, &cz);
    float cycx = cy * cx, sysx = sy * sx, sycx = sy * cx, cysx = cy * sx;
    float* u = g_gates + g * 8;
    u[0] =  cz * cycx + sz * sysx;   // u00r
    u[1] =  cz * sysx - sz * cycx;   // u00i
    u[2] = -cz * sycx - sz * cysx;   // u01r
    u[3] =  sz * sycx - cz * cysx;   // u01i
    u[4] =  cz * sycx + sz * cysx;   // u10r  (= -u01r)
    u[5] =  sz * sycx - cz * cysx;   // u10i  (=  u01i)
    u[6] =  cz * cycx + sz * sysx;   // u11r  (=  u00r)
    u[7] =  sz * cycx - cz * sysx;   // u11i  (= -u00i)
}

__device__ __forceinline__ void load_gate(int layer, int wire, float4& u0, float4& u1) {
    const float4* p = reinterpret_cast<const float4*>(g_gates) + (layer * 16 + wire) * 2;
    u0 = p[0];
    u1 = p[1];
}

__device__ __forceinline__ void cgate(float2& p0, float2& p1, float4 u0, float4 u1) {
    float a0r = p0.x, a0i = p0.y, a1r = p1.x, a1i = p1.y;
    p0.x = u0.x * a0r - u0.y * a0i + u0.z * a1r - u0.w * a1i;
    p0.y = u0.x * a0i + u0.y * a0r + u0.z * a1i + u0.w * a1r;
    p1.x = u1.x * a0r - u1.y * a0i + u1.z * a1r - u1.w * a1i;
    p1.y = u1.x * a0i + u1.y * a0r + u1.z * a1i + u1.w * a1r;
}

template <int BIT>
__device__ __forceinline__ void apply_local(float2 v[16], float4 u0, float4 u1) {
    constexpr int S = 1 << BIT;
#pragma unroll
    for (int base = 0; base < 16; base += 2 * S)
#pragma unroll
        for (int off = 0; off < S; off++)
            cgate(v[base + off], v[base + off + S], u0, u1);
}

// ---------------------------------------------------------------------------
// Pass B: gates on wires 0..3 (bits 15..12). One thread owns 16 amplitudes at
// stride 4096. mode 0: read planar inputs -> buf0.
//          mode 1: read buf0 with Gray gather -> buf1.
//          mode 2: read buf1 with Gray gather -> buf0.
// ---------------------------------------------------------------------------
__global__ void __launch_bounds__(256) pass_high(int layer, int mode,
                                                 const float* __restrict__ sr,
                                                 const float* __restrict__ si) {
    unsigned batch = blockIdx.x >> 4;
    unsigned j = ((blockIdx.x & 15u) << 8) | threadIdx.x;   // low 12 bits
    unsigned base = batch << 16;

    float2 v[16];
    if (mode == 0) {
#pragma unroll
        for (int h = 0; h < 16; h++) {
            unsigned idx = base + ((unsigned)h << 12) + j;
            v[h] = make_float2(sr[idx], si[idx]);
        }
    } else {
        const float2* __restrict__ src = (mode == 1) ? g_buf0 : g_buf1;
        unsigned jg = j ^ (j >> 1);
#pragma unroll
        for (int h = 0; h < 16; h++) {
            unsigned hg = (unsigned)h ^ ((unsigned)h >> 1);
            unsigned lo = jg ^ ((h & 1u) << 11);
            v[h] = src[base + (hg << 12) + lo];
        }
    }

    float4 u0, u1;
    load_gate(layer, 0, u0, u1); apply_local<3>(v, u0, u1);   // wire0 <-> h bit3
    load_gate(layer, 1, u0, u1); apply_local<2>(v, u0, u1);
    load_gate(layer, 2, u0, u1); apply_local<1>(v, u0, u1);
    load_gate(layer, 3, u0, u1); apply_local<0>(v, u0, u1);

    float2* __restrict__ dst = (mode == 1) ? g_buf1 : g_buf0;
#pragma unroll
    for (int h = 0; h < 16; h++)
        dst[base + ((unsigned)h << 12) + j] = v[h];
}

// XOR swizzle over float2 indices (16 bank-pairs of 8B)
__device__ __forceinline__ unsigned sw(unsigned a) { return a ^ ((a >> 4) & 15u); }

// ---------------------------------------------------------------------------
// Pass A: gates on wires 4..15 (bits 11..0), in-place. One CTA per 4096-amp
// chunk. 3 register rounds (4 gates each) with 2 swizzled smem exchanges.
// final=1: instead of writing the state, fold the layer-3 Gray permutation
// into Pauli-Z signs and accumulate the head dot-product per chunk.
// ---------------------------------------------------------------------------
__global__ void __launch_bounds__(256) pass_low(int layer, int which, int final_pass,
                                                const float* __restrict__ hw) {
    __shared__ float2 sh[4096];
    __shared__ float red[8];
    float2* __restrict__ buf = which ? g_buf1 : g_buf0;

    unsigned batch = blockIdx.x >> 4;
    unsigned H = blockIdx.x & 15u;               // high nibble of state index
    unsigned cbase = (batch << 16) | (H << 12);
    unsigned t = threadIdx.x;

    float2 v[16];

    // Round 1: thread owns bits 11..8  (a = k<<8 | t) — coalesced global load
#pragma unroll
    for (int k = 0; k < 16; k++) v[k] = buf[cbase + ((unsigned)k << 8) + t];
    {
        float4 u0, u1;
        load_gate(layer, 7, u0, u1); apply_local<0>(v, u0, u1);   // bit 8
        load_gate(layer, 6, u0, u1); apply_local<1>(v, u0, u1);   // bit 9
        load_gate(layer, 5, u0, u1); apply_local<2>(v, u0, u1);   // bit 10
        load_gate(layer, 4, u0, u1); apply_local<3>(v, u0, u1);   // bit 11
    }

    // Exchange -> Round 2: thread owns bits 7..4
#pragma unroll
    for (int k = 0; k < 16; k++) sh[sw(((unsigned)k << 8) | t)] = v[k];
    __syncthreads();
    unsigned hi = (t >> 4) << 8, lo = t & 15u;
#pragma unroll
    for (int k = 0; k < 16; k++) v[k] = sh[sw(hi | ((unsigned)k << 4) | lo)];
    {
        float4 u0, u1;
        load_gate(layer, 11, u0, u1); apply_local<0>(v, u0, u1);  // bit 4
        load_gate(layer, 10, u0, u1); apply_local<1>(v, u0, u1);  // bit 5
        load_gate(layer,  9, u0, u1); apply_local<2>(v, u0, u1);  // bit 6
        load_gate(layer,  8, u0, u1); apply_local<3>(v, u0, u1);  // bit 7
    }
    __syncthreads();

    // Exchange -> Round 3: thread owns bits 3..0
#pragma unroll
    for (int k = 0; k < 16; k++) sh[sw(hi | ((unsigned)k << 4) | lo)] = v[k];
    __syncthreads();
#pragma unroll
    for (int k = 0; k < 16; k++) v[k] = sh[sw((t << 4) | (unsigned)k)];
    {
        float4 u0, u1;
        load_gate(layer, 15, u0, u1); apply_local<0>(v, u0, u1);  // bit 0
        load_gate(layer, 14, u0, u1); apply_local<1>(v, u0, u1);  // bit 1
        load_gate(layer, 13, u0, u1); apply_local<2>(v, u0, u1);  // bit 2
        load_gate(layer, 12, u0, u1); apply_local<3>(v, u0, u1);  // bit 3
    }

    if (!final_pass) {
        // vectorized in-place store (a = t<<4 | k)
#pragma unroll
        for (int k = 0; k < 16; k += 2) {
            float4 w = make_float4(v[k].x, v[k].y, v[k + 1].x, v[k + 1].y);
            *reinterpret_cast<float4*>(&buf[cbase + (t << 4) + (unsigned)k]) = w;
        }
    } else {
        // Final epilogue: psi_final[b] = psi_rot[gray(b)]; bit q of b (at
        // position 15-q) = parity(s >> (15-q)) for stored index s.
        // coeff(s) = sum_q hw[q] * (+1 if that parity is 0 else -1).
        float w[16];
#pragma unroll
        for (int q = 0; q < 16; q++) w[q] = hw[q];

        unsigned shi = (H << 8) | t;   // bits 15..4 of s
        int run = 0; float c0 = 0.f;
#pragma unroll
        for (int q = 0; q <= 11; q++) {
            run ^= (int)((shi >> (11 - q)) & 1u);
            c0 += run ? -w[q] : w[q];
        }
        float acc = 0.f;
#pragma unroll
        for (int k = 0; k < 16; k++) {
            int r = run; float c = c0;
            r ^= (k >> 3) & 1; c += r ? -w[12] : w[12];
            r ^= (k >> 2) & 1; c += r ? -w[13] : w[13];
            r ^= (k >> 1) & 1; c += r ? -w[14] : w[14];
            r ^=  k       & 1; c += r ? -w[15] : w[15];
            acc += (v[k].x * v[k].x + v[k].y * v[k].y) * c;
        }
        // block reduction
#pragma unroll
        for (int o = 16; o > 0; o >>= 1)
            acc += __shfl_down_sync(0xffffffffu, acc, o);
        if ((t & 31u) == 0) red[t >> 5] = acc;
        __syncthreads();
        if (t == 0) {
            float s = 0.f;
#pragma unroll
            for (int i = 0; i < 8; i++) s += red[i];
            g_partial[(batch << 4) | H] = s;
        }
    }
}

__global__ void head_kernel(float* __restrict__ out, const float* __restrict__ hb) {
    int b = threadIdx.x;
    if (b < BATCH) {
        float s = hb[0];
#pragma unroll
        for (int c = 0; c < 16; c++) s += g_partial[(b << 4) | c];
        out[b] = s;
    }
}

// ---------------------------------------------------------------------------
extern "C" void kernel_launch(void* const* d_in, const int* in_sizes, int n_in,
                              void* d_out, int out_size) {
    const float* sr = (const float*)d_in[0];
    const float* si = (const float*)d_in[1];
    const float* vp = (const float*)d_in[2];
    const float* hw = (const float*)d_in[3];
    const float* hb = (const float*)d_in[4];
    float* out = (float*)d_out;
    (void)in_sizes; (void)n_in; (void)out_size;

    prep_gates<<<1, 64>>>(vp);

    // layer 0
    pass_high<<<1024, 256>>>(0, 0, sr, si);            // inputs -> buf0
    pass_low <<<1024, 256>>>(0, 0, 0, hw);             // buf0 in place
    // layer 1 (Gray of layer 0 fused into gather)
    pass_high<<<1024, 256>>>(1, 1, nullptr, nullptr);  // buf0 -> buf1
    pass_low <<<1024, 256>>>(1, 1, 0, hw);             // buf1 in place
    // layer 2
    pass_high<<<1024, 256>>>(2, 2, nullptr, nullptr);  // buf1 -> buf0
    pass_low <<<1024, 256>>>(2, 0, 1, hw);             // buf0 -> partial feats

    head_kernel<<<1, 64>>>(out, hb);
}

// round 4
// speedup vs baseline: 1.0147x; 1.0147x over previous
#include <cuda_runtime.h>

// ---------------------------------------------------------------------------
// 16-qubit statevector sim, batch 64, batch-PAIR packed into f32x2 lanes.
//
//  * Per layer: Pass B = wires 0..3 (bits 15..12), Pass A = wires 4..15.
//  * CNOT chain == Gray-code permutation psi'[b] = psi[b ^ (b>>1)], fused
//    into the next Pass B gather and into the final Pauli-Z sign pattern.
//  * Two batch elements ride in one 64-bit register pair; every gate is
//    applied with fma.rn.f32x2 (FFMA2), halving the FMA instruction count.
//  * Intermediate buffers are pair-major split-complex so packed values are
//    loaded/stored directly (no pack/unpack instructions in steady state).
// ---------------------------------------------------------------------------

typedef unsigned long long ull;

#define DIM   65536
#define BATCH 64
#define NPAIR 32

__device__ ull g_bufr0[NPAIR * DIM];   // 16 MB each
__device__ ull g_bufi0[NPAIR * DIM];
__device__ ull g_bufr1[NPAIR * DIM];
__device__ ull g_bufi1[NPAIR * DIM];
__device__ __align__(16) float g_gates[3 * 16 * 8];
__device__ float2 g_partial[NPAIR * 16];

// ---------------- f32x2 helpers ----------------
__device__ __forceinline__ ull dup2(float v) {
    ull r; asm("mov.b64 %0, {%1, %1};" : "=l"(r) : "f"(v)); return r;
}
__device__ __forceinline__ ull pk2(float a, float b) {
    ull r; asm("mov.b64 %0, {%1, %2};" : "=l"(r) : "f"(a), "f"(b)); return r;
}
__device__ __forceinline__ float2 up2(ull v) {
    float2 r; asm("mov.b64 {%0, %1}, %2;" : "=f"(r.x), "=f"(r.y) : "l"(v)); return r;
}
__device__ __forceinline__ ull ffma2(ull a, ull b, ull c) {
    ull d; asm("fma.rn.f32x2 %0, %1, %2, %3;" : "=l"(d) : "l"(a), "l"(b), "l"(c)); return d;
}
__device__ __forceinline__ ull fmul2(ull a, ull b) {
    ull d; asm("mul.rn.f32x2 %0, %1, %2;" : "=l"(d) : "l"(a), "l"(b)); return d;
}

// ---------------------------------------------------------------------------
// Gate precompute: U = Rz Ry Rx as (u00r,u00i,u01r,u01i, u10r,u10i,u11r,u11i)
// (u10 = (-u01r, u01i), u11 = (u00r, -u00i) — exploited in cgateP)
// ---------------------------------------------------------------------------
__global__ void prep_gates(const float* __restrict__ vp) {
    int g = threadIdx.x;
    if (g >= 48) return;
    float tx = vp[g * 6 + 0], ty = vp[g * 6 + 1], tz = vp[g * 6 + 2];
    float cx, sx, cy, sy, cz, sz;
    sincosf(tx * 0.5f, &sx, &cx);
    sincosf(ty * 0.5f, &sy, &cy);
    sincosf(tz * 0.5f, &sz, &cz);
    float cycx = cy * cx, sysx = sy * sx, sycx = sy * cx, cysx = cy * sx;
    float* u = g_gates + g * 8;
    u[0] =  cz * cycx + sz * sysx;
    u[1] =  cz * sysx - sz * cycx;
    u[2] = -cz * sycx - sz * cysx;
    u[3] =  sz * sycx - cz * cysx;
    u[4] = -u[2];
    u[5] =  u[3];
    u[6] =  u[0];
    u[7] = -u[1];
}

struct GateP { ull c00r, c00i, n00i, c01r, n01r, c01i, n01i; };

__device__ __forceinline__ GateP load_gateP(int layer, int wire) {
    const float4* p = reinterpret_cast<const float4*>(g_gates) + (layer * 16 + wire) * 2;
    float4 u0 = p[0];
    GateP g;
    g.c00r = dup2(u0.x); g.c00i = dup2(u0.y); g.n00i = dup2(-u0.y);
    g.c01r = dup2(u0.z); g.n01r = dup2(-u0.z);
    g.c01i = dup2(u0.w); g.n01i = dup2(-u0.w);
    return g;
}

__device__ __forceinline__ void cgateP(ull& a0r, ull& a0i, ull& a1r, ull& a1i,
                                       const GateP& g) {
    ull p0r = ffma2(g.c00r, a0r, ffma2(g.n00i, a0i, ffma2(g.c01r, a1r, fmul2(g.n01i, a1i))));
    ull p0i = ffma2(g.c00r, a0i, ffma2(g.c00i, a0r, ffma2(g.c01r, a1i, fmul2(g.c01i, a1r))));
    ull p1r = ffma2(g.n01r, a0r, ffma2(g.n01i, a0i, ffma2(g.c00r, a1r, fmul2(g.c00i, a1i))));
    ull p1i = ffma2(g.n01r, a0i, ffma2(g.c01i, a0r, ffma2(g.c00r, a1i, fmul2(g.n00i, a1r))));
    a0r = p0r; a0i = p0i; a1r = p1r; a1i = p1i;
}

template <int BIT>
__device__ __forceinline__ void apply_localP(ull vr[16], ull vi[16], const GateP& g) {
    constexpr int S = 1 << BIT;
#pragma unroll
    for (int base = 0; base < 16; base += 2 * S)
#pragma unroll
        for (int off = 0; off < S; off++)
            cgateP(vr[base + off], vi[base + off], vr[base + off + S], vi[base + off + S], g);
}

// ---------------------------------------------------------------------------
// Pass B: wires 0..3 (bits 15..12). Thread owns 16 packed amps at stride 4096.
// mode 0: planar inputs -> buf0 (packs two batch planes).
// mode 1: buf0 --Gray gather--> buf1.   mode 2: buf1 --Gray gather--> buf0.
// ---------------------------------------------------------------------------
__global__ void __launch_bounds__(256, 2) pass_high(int layer, int mode,
                                                    const float* __restrict__ sr,
                                                    const float* __restrict__ si) {
    unsigned pair = blockIdx.x >> 4;
    unsigned j = ((blockIdx.x & 15u) << 8) | threadIdx.x;   // low 12 bits
    unsigned base = pair << 16;

    ull vr[16], vi[16];
    if (mode == 0) {
        unsigned b0 = (pair << 1) << 16, b1 = ((pair << 1) | 1u) << 16;
#pragma unroll
        for (int h = 0; h < 16; h++) {
            unsigned idx = ((unsigned)h << 12) + j;
            vr[h] = pk2(sr[b0 + idx], sr[b1 + idx]);
            vi[h] = pk2(si[b0 + idx], si[b1 + idx]);
        }
    } else {
        const ull* __restrict__ srcr = (mode == 1) ? g_bufr0 : g_bufr1;
        const ull* __restrict__ srci = (mode == 1) ? g_bufi0 : g_bufi1;
        unsigned jg = j ^ (j >> 1);
#pragma unroll
        for (int h = 0; h < 16; h++) {
            unsigned hg = (unsigned)h ^ ((unsigned)h >> 1);
            unsigned lo = jg ^ ((h & 1u) << 11);
            unsigned idx = base + (hg << 12) + lo;
            vr[h] = srcr[idx];
            vi[h] = srci[idx];
        }
    }

    { GateP g = load_gateP(layer, 0); apply_localP<3>(vr, vi, g); }
    { GateP g = load_gateP(layer, 1); apply_localP<2>(vr, vi, g); }
    { GateP g = load_gateP(layer, 2); apply_localP<1>(vr, vi, g); }
    { GateP g = load_gateP(layer, 3); apply_localP<0>(vr, vi, g); }

    ull* __restrict__ dr = (mode == 1) ? g_bufr1 : g_bufr0;
    ull* __restrict__ di = (mode == 1) ? g_bufi1 : g_bufi0;
#pragma unroll
    for (int h = 0; h < 16; h++) {
        unsigned idx = base + ((unsigned)h << 12) + j;
        dr[idx] = vr[h];
        di[idx] = vi[h];
    }
}

// XOR swizzle over 8B words
__device__ __forceinline__ unsigned sw(unsigned a) { return a ^ ((a >> 4) & 15u); }

// ---------------------------------------------------------------------------
// Pass A: wires 4..15 (bits 11..0), in-place per 4096-amp chunk (one CTA).
// 3 register rounds with 2 swizzled smem exchanges (dynamic smem, 64 KB).
// final_pass=1: fold layer-3 Gray into Pauli-Z signs, accumulate head dot.
// ---------------------------------------------------------------------------
__global__ void __launch_bounds__(256, 2) pass_low(int layer, int which, int final_pass,
                                                   const float* __restrict__ hw) {
    extern __shared__ ull smem_dyn[];
    ull* shr = smem_dyn;
    ull* shi = smem_dyn + 4096;
    __shared__ float2 red[8];

    ull* __restrict__ bufr = which ? g_bufr1 : g_bufr0;
    ull* __restrict__ bufi = which ? g_bufi1 : g_bufi0;

    unsigned pair = blockIdx.x >> 4;
    unsigned H = blockIdx.x & 15u;
    unsigned cb = (pair << 16) | (H << 12);
    unsigned t = threadIdx.x;

    ull vr[16], vi[16];

    // Round 1: thread owns bits 11..8 (a = k<<8 | t)
#pragma unroll
    for (int k = 0; k < 16; k++) {
        unsigned idx = cb + ((unsigned)k << 8) + t;
        vr[k] = bufr[idx];
        vi[k] = bufi[idx];
    }
    { GateP g = load_gateP(layer, 7); apply_localP<0>(vr, vi, g); }   // bit 8
    { GateP g = load_gateP(layer, 6); apply_localP<1>(vr, vi, g); }   // bit 9
    { GateP g = load_gateP(layer, 5); apply_localP<2>(vr, vi, g); }   // bit 10
    { GateP g = load_gateP(layer, 4); apply_localP<3>(vr, vi, g); }   // bit 11

    // Exchange -> Round 2: thread owns bits 7..4
#pragma unroll
    for (int k = 0; k < 16; k++) {
        unsigned a = sw(((unsigned)k << 8) | t);
        shr[a] = vr[k]; shi[a] = vi[k];
    }
    __syncthreads();
    unsigned hi = (t >> 4) << 8, lo = t & 15u;
#pragma unroll
    for (int k = 0; k < 16; k++) {
        unsigned a = sw(hi | ((unsigned)k << 4) | lo);
        vr[k] = shr[a]; vi[k] = shi[a];
    }
    { GateP g = load_gateP(layer, 11); apply_localP<0>(vr, vi, g); }  // bit 4
    { GateP g = load_gateP(layer, 10); apply_localP<1>(vr, vi, g); }  // bit 5
    { GateP g = load_gateP(layer,  9); apply_localP<2>(vr, vi, g); }  // bit 6
    { GateP g = load_gateP(layer,  8); apply_localP<3>(vr, vi, g); }  // bit 7
    __syncthreads();

    // Exchange -> Round 3: thread owns bits 3..0
#pragma unroll
    for (int k = 0; k < 16; k++) {
        unsigned a = sw(hi | ((unsigned)k << 4) | lo);
        shr[a] = vr[k]; shi[a] = vi[k];
    }
    __syncthreads();
#pragma unroll
    for (int k = 0; k < 16; k++) {
        unsigned a = sw((t << 4) | (unsigned)k);
        vr[k] = shr[a]; vi[k] = shi[a];
    }
    { GateP g = load_gateP(layer, 15); apply_localP<0>(vr, vi, g); }  // bit 0
    { GateP g = load_gateP(layer, 14); apply_localP<1>(vr, vi, g); }  // bit 1
    { GateP g = load_gateP(layer, 13); apply_localP<2>(vr, vi, g); }  // bit 2
    { GateP g = load_gateP(layer, 12); apply_localP<3>(vr, vi, g); }  // bit 3

    if (!final_pass) {
        // vectorized in-place store (a = t<<4 | k), 16B per store
#pragma unroll
        for (int k = 0; k < 16; k += 2) {
            unsigned idx = cb + (t << 4) + (unsigned)k;
            *reinterpret_cast<ulonglong2*>(&bufr[idx]) = make_ulonglong2(vr[k], vr[k + 1]);
            *reinterpret_cast<ulonglong2*>(&bufi[idx]) = make_ulonglong2(vi[k], vi[k + 1]);
        }
    } else {
        // psi_final[b] = psi_rot[gray(b)]; bit at position (15-q) of b equals
        // parity(s >> (15-q)) for stored index s. coeff(s) = sum_q ±hw[q].
        float w[16];
#pragma unroll
        for (int q = 0; q < 16; q++) w[q] = hw[q];

        unsigned shidx = (H << 8) | t;   // bits 15..4 of s
        int run = 0; float c0 = 0.f;
#pragma unroll
        for (int q = 0; q <= 11; q++) {
            run ^= (int)((shidx >> (11 - q)) & 1u);
            c0 += run ? -w[q] : w[q];
        }
        ull acc = dup2(0.f);
#pragma unroll
        for (int k = 0; k < 16; k++) {
            int r = run; float c = c0;
            r ^= (k >> 3) & 1; c += r ? -w[12] : w[12];
            r ^= (k >> 2) & 1; c += r ? -w[13] : w[13];
            r ^= (k >> 1) & 1; c += r ? -w[14] : w[14];
            r ^=  k       & 1; c += r ? -w[15] : w[15];
            ull prob = ffma2(vr[k], vr[k], fmul2(vi[k], vi[k]));
            acc = ffma2(dup2(c), prob, acc);
        }
        float2 a = up2(acc);
#pragma unroll
        for (int o = 16; o > 0; o >>= 1) {
            a.x += __shfl_down_sync(0xffffffffu, a.x, o);
            a.y += __shfl_down_sync(0xffffffffu, a.y, o);
        }
        if ((t & 31u) == 0) red[t >> 5] = a;
        __syncthreads();
        if (t == 0) {
            float2 s = make_float2(0.f, 0.f);
#pragma unroll
            for (int i = 0; i < 8; i++) { s.x += red[i].x; s.y += red[i].y; }
            g_partial[(pair << 4) | H] = s;
        }
    }
}

__global__ void head_kernel(float* __restrict__ out, const float* __restrict__ hb) {
    int b = threadIdx.x;
    if (b < BATCH) {
        float s = hb[0];
        int pair = b >> 1;
#pragma unroll
        for (int c = 0; c < 16; c++) {
            float2 p = g_partial[(pair << 4) | c];
            s += (b & 1) ? p.y : p.x;
        }
        out[b] = s;
    }
}

// ---------------------------------------------------------------------------
extern "C" void kernel_launch(void* const* d_in, const int* in_sizes, int n_in,
                              void* d_out, int out_size) {
    const float* sr = (const float*)d_in[0];
    const float* si = (const float*)d_in[1];
    const float* vp = (const float*)d_in[2];
    const float* hw = (const float*)d_in[3];
    const float* hb = (const float*)d_in[4];
    float* out = (float*)d_out;
    (void)in_sizes; (void)n_in; (void)out_size;

    cudaFuncSetAttribute(pass_low, cudaFuncAttributeMaxDynamicSharedMemorySize, 65536);

    prep_gates<<<1, 64>>>(vp);

    // layer 0
    pass_high<<<512, 256>>>(0, 0, sr, si);                     // inputs -> buf0
    pass_low <<<512, 256, 65536>>>(0, 0, 0, hw);               // buf0 in place
    // layer 1 (Gray of layer 0 fused into gather)
    pass_high<<<512, 256>>>(1, 1, nullptr, nullptr);           // buf0 -> buf1
    pass_low <<<512, 256, 65536>>>(1, 1, 0, hw);               // buf1 in place
    // layer 2
    pass_high<<<512, 256>>>(2, 2, nullptr, nullptr);           // buf1 -> buf0
    pass_low <<<512, 256, 65536>>>(2, 0, 1, hw);               // buf0 -> partials

    head_kernel<<<1, 64>>>(out, hb);
}